// round 6
// baseline (speedup 1.0000x reference)
#include <cuda_runtime.h>
#include <stdint.h>

// Problem constants (fixed shapes)
#define NN   10000       // nodes
#define BB   4           // batch
#define FIN  16          // input features
#define TT   8           // time steps
#define CCH  32          // cheb channels
#define CTM  64          // time channels
#define MAXE 160000      // edges
#define ITERS 64         // power iterations
#define PB   80          // power-iteration blocks (co-resident, < 148 SMs)
#define PT   128
#define TOTX (NN*512)    // Tx element count = N * TB(32) * F(16)

// ---------------- scratch (device globals; no allocation) ----------------
__device__ __align__(16) float g_Tx0[TOTX];
__device__ __align__(16) float g_Tx1[TOTX];
__device__ __align__(16) float g_cheb[NN*1024];   // [n][tb(32)][c(32)]
__device__ int   g_indeg[NN];
__device__ int   g_rowptr[NN+1];
__device__ int   g_cursor[NN];
__device__ int   g_col[MAXE];
__device__ float g_u0[NN];
__device__ float g_u1[NN];
__device__ float g_S[ITERS+1];
__device__ float g_lmax;
__device__ float g_diag[NN];
__device__ int   g_bar_count;
__device__ int   g_bar_gen;

// ---------------- packed f32x2 helpers (sm_100a) -------------------------
__device__ __forceinline__ unsigned long long pk2(float a, float b) {
    unsigned long long r;
    asm("mov.b64 %0, {%1, %2};" : "=l"(r) : "f"(a), "f"(b));
    return r;
}
__device__ __forceinline__ void fma2(unsigned long long& d, unsigned long long a, unsigned long long b) {
    asm("fma.rn.f32x2 %0, %1, %2, %0;" : "+l"(d) : "l"(a), "l"(b));
}
__device__ __forceinline__ float2 upk2(unsigned long long v) {
    float2 f;
    asm("mov.b64 {%0, %1}, %2;" : "=f"(f.x), "=f"(f.y) : "l"(v));
    return f;
}

// ---------------- software grid barrier (PB co-resident blocks) ----------
__device__ __forceinline__ void grid_bar() {
    __syncthreads();
    if (threadIdx.x == 0) {
        volatile int* gen = &g_bar_gen;
        int g = *gen;
        __threadfence();
        if (atomicAdd(&g_bar_count, 1) == PB - 1) {
            atomicExch(&g_bar_count, 0);
            __threadfence();
            atomicAdd(&g_bar_gen, 1);
        } else {
            while (*gen == g) { }
            __threadfence();
        }
    }
    __syncthreads();
}

// ---------------- CSR build --------------------------------------------
__global__ void k_zero() {
    int i = blockIdx.x * blockDim.x + threadIdx.x;
    if (i < NN) g_indeg[i] = 0;
}

__global__ void k_hist(const int* __restrict__ dst, int E) {
    int e = blockIdx.x * blockDim.x + threadIdx.x;
    if (e < E) atomicAdd(&g_indeg[dst[e]], 1);
}

__global__ void k_scan() {   // 1 block, 1024 threads
    __shared__ int ps[1024];
    const int CH = 10;       // 1024*10 >= NN
    int t = threadIdx.x;
    int base = t * CH;
    int sum = 0;
#pragma unroll
    for (int i = 0; i < CH; i++) { int idx = base + i; if (idx < NN) sum += g_indeg[idx]; }
    ps[t] = sum; __syncthreads();
    for (int off = 1; off < 1024; off <<= 1) {
        int v = ps[t];
        int a = (t >= off) ? ps[t - off] : 0;
        __syncthreads();
        ps[t] = v + a;
        __syncthreads();
    }
    int run = (t == 0) ? 0 : ps[t - 1];
#pragma unroll
    for (int i = 0; i < CH; i++) {
        int idx = base + i;
        if (idx < NN) { g_rowptr[idx] = run; g_cursor[idx] = run; run += g_indeg[idx]; }
    }
    if (t == 1023) g_rowptr[NN] = ps[1023];
}

__global__ void k_fill(const int* __restrict__ src, const int* __restrict__ dst, int E) {
    int e = blockIdx.x * blockDim.x + threadIdx.x;
    if (e < E) {
        int p = atomicAdd(&g_cursor[dst[e]], 1);
        g_col[p] = src[e];
    }
}

// ---------------- power iteration (persistent, 64 iters) ----------------
// Iteration 1: v0 = const c is in the null space of L, so M v0 is pure fp32
// rounding residue, replicated exactly (chain-sum, unfused mul/sub).
// Iterations 2+: one node per thread; 64 predicated gathers issued up front
// (full MLP), accumulation order identical to a sequential edge loop
// (subtracting masked 0.0f is exact).
__global__ void k_power() {
    const int TH = PB * PT;
    const float C0 = 0.01f;                 // 1/sqrt(10000) rounded to f32
    int gt = blockIdx.x * PT + threadIdx.x;
    __shared__ float red[PT];

    for (int i = gt; i <= ITERS; i += TH) g_S[i] = (i == 0) ? 1.0f : 0.0f;

    bool valid = gt < NN;
    int n = gt;
    int e0 = 0, m = 0; float degf = 0.f;
    if (valid) {
        e0 = g_rowptr[n];
        m  = g_rowptr[n + 1] - e0;
        degf = (float)g_indeg[n];
    }
    grid_bar();

    float* ua = g_u0;
    float* ub = g_u1;
    for (int k = 1; k <= ITERS; k++) {
        float part = 0.0f;
        if (k == 1) {
            if (valid) {
                float av = 0.0f;
                for (int j = 0; j < m; j++) av = __fadd_rn(av, C0);
                float w = __fsub_rn(__fmul_rn(degf, C0), av);
                ub[n] = w;
                part = w * w;
            }
        } else {
            float inv = 1.0f / sqrtf(__ldcg(&g_S[k - 1]));
            if (valid) {
                float acc = degf * __ldcg(&ua[n]);
#pragma unroll
                for (int j = 0; j < 64; j++) {
                    int idx = (j < m) ? (e0 + j) : 0;
                    float v = __ldcg(&ua[g_col[idx]]);
                    acc -= (j < m) ? v : 0.0f;
                }
                for (int j = 64; j < m; j++) acc -= __ldcg(&ua[g_col[e0 + j]]);
                acc *= inv;
                ub[n] = acc;
                part = acc * acc;
            }
        }
        red[threadIdx.x] = part; __syncthreads();
        for (int s = PT / 2; s > 0; s >>= 1) {
            if (threadIdx.x < s) red[threadIdx.x] += red[threadIdx.x + s];
            __syncthreads();
        }
        if (threadIdx.x == 0) atomicAdd(&g_S[k], red[0]);
        grid_bar();
        float* tmp = ua; ua = ub; ub = tmp;
    }
    float lm = sqrtf(__ldcg(&g_S[ITERS]));
    if (gt == 0) g_lmax = lm;
    for (int i = gt; i < NN; i += TH)
        g_diag[i] = 2.0f * (float)g_indeg[i] / lm - 1.0f;
}

// ---------------- permute X -> Tx0 [n2][tb][f] --------------------------
// Reference: (B,N,F,T) -transpose(2,0,1,3)-> (F,B,N,T) -reshape-> (N2,F2,TB) -transpose(2,0,1)
__global__ void k_permute(const float* __restrict__ X) {
    int o = blockIdx.x * blockDim.x + threadIdx.x;
    if (o >= TOTX) return;
    int n2 = o >> 9;
    int r  = o & 511;
    int tb = r >> 4, f2 = r & 15;
    int s = (n2 << 9) + (f2 << 5) + tb;        // flat idx in (F,B,N,T)
    int f  = s / 320000; int s2 = s - f * 320000;   // 320000 = B*N*T
    int b  = s2 / 80000; int s3 = s2 - b * 80000;   // 80000 = N*T
    int n  = s3 >> 3;    int t  = s3 & 7;
    g_Tx0[o] = X[(((b * NN + n) << 4) + f) * 8 + t];
}

// ---------------- lhat1: Tx1 = diag*Tx0 - off * A^T Tx0 -----------------
__global__ void k_lhat1() {
    int n = blockIdx.x;
    int t = threadIdx.x;   // 0..127, float4 chunk of the 512-channel row
    const float4* x0 = reinterpret_cast<const float4*>(g_Tx0);
    float4 acc = make_float4(0.f, 0.f, 0.f, 0.f);
    int e0 = g_rowptr[n], e1 = g_rowptr[n + 1];
    for (int j = e0; j < e1; j++) {
        int s = g_col[j];
        float4 v = x0[s * 128 + t];
        acc.x += v.x; acc.y += v.y; acc.z += v.z; acc.w += v.w;
    }
    float off = 2.0f / g_lmax;
    float dg  = g_diag[n];
    float4 xx = x0[n * 128 + t];
    float4 o;
    o.x = dg * xx.x - off * acc.x;
    o.y = dg * xx.y - off * acc.y;
    o.z = dg * xx.z - off * acc.z;
    o.w = dg * xx.w - off * acc.w;
    reinterpret_cast<float4*>(g_Tx1)[n * 128 + t] = o;
}

// ------- lhat2 (Tx2 = 2*lhat(Tx1)-Tx0) fused with Cheb GEMM + ReLU ------
__global__ void k_lhat2cheb(const float* __restrict__ chebW, const float* __restrict__ chebB) {
    __shared__ __align__(16) float sT[1536];   // Tx0,Tx1,Tx2 rows of this node
    __shared__ float sW[1536];                 // cheb_W (3,16,32)
    __shared__ float sB[CCH];
    int n = blockIdx.x;
    int t = threadIdx.x;   // 128 threads
    for (int i = t; i < 1536; i += 128) sW[i] = chebW[i];
    if (t < CCH) sB[t] = chebB[t];

    const float4* x0 = reinterpret_cast<const float4*>(g_Tx0);
    const float4* x1 = reinterpret_cast<const float4*>(g_Tx1);
    float4 acc = make_float4(0.f, 0.f, 0.f, 0.f);
    int e0 = g_rowptr[n], e1 = g_rowptr[n + 1];
    for (int j = e0; j < e1; j++) {
        int s = g_col[j];
        float4 v = x1[s * 128 + t];
        acc.x += v.x; acc.y += v.y; acc.z += v.z; acc.w += v.w;
    }
    float off = 2.0f / g_lmax;
    float dg  = g_diag[n];
    float4 a1 = x1[n * 128 + t];
    float4 a0 = x0[n * 128 + t];
    float4 t2;
    t2.x = 2.f * (dg * a1.x - off * acc.x) - a0.x;
    t2.y = 2.f * (dg * a1.y - off * acc.y) - a0.y;
    t2.z = 2.f * (dg * a1.z - off * acc.z) - a0.z;
    t2.w = 2.f * (dg * a1.w - off * acc.w) - a0.w;
    reinterpret_cast<float4*>(sT)[t]       = a0;   // Tx0 row
    reinterpret_cast<float4*>(sT)[128 + t] = a1;   // Tx1 row
    reinterpret_cast<float4*>(sT)[256 + t] = t2;   // Tx2 row
    __syncthreads();

    // out[tb][c] = relu(b_c + sum_k sum_f Txk[tb][f]*W[k][f][c])
    int tb = t >> 2;
    int c0 = (t & 3) << 3;   // 8 channels per thread
    float y[8];
#pragma unroll
    for (int i = 0; i < 8; i++) y[i] = 0.f;
#pragma unroll
    for (int k = 0; k < 3; k++) {
        const float* xr = sT + k * 512 + tb * 16;
        const float* wk = sW + k * 512;
#pragma unroll
        for (int f = 0; f < FIN; f++) {
            float xv = xr[f];
            const float* wr = wk + f * 32 + c0;
#pragma unroll
            for (int i = 0; i < 8; i++) y[i] += xv * wr[i];
        }
    }
    float* outp = g_cheb + n * 1024 + tb * 32 + c0;
#pragma unroll
    for (int i = 0; i < 8; i++) outp[i] = fmaxf(y[i] + sB[c0 + i], 0.f);
}

// ------- final: time conv + residual + ReLU + LayerNorm + write ---------
// per (b,n) unit: Y(64x8) = A(64x112) * Z(112x8) + bias ; relu ; LN over 64
// GEMM uses packed fma.rn.f32x2 (identical rounding to scalar FFMA chain).
__global__ void k_final(const float* __restrict__ X,
                        const float* __restrict__ timeW, const float* __restrict__ timeB,
                        const float* __restrict__ resW,  const float* __restrict__ resB,
                        const float* __restrict__ gamma, const float* __restrict__ beta,
                        float* __restrict__ out) {
    __shared__ float As[112 * 64];                   // transposed: As[kk*64+co]
    __shared__ __align__(16) float Zs[4][896];       // per-group Z (112x8)
    __shared__ float sBias[64], sG[64], sBt[64];
    __shared__ float redS[4][2][8], redQ[4][2][8];
    int tid = threadIdx.x;

    for (int i = tid; i < 7168; i += 256) {
        int kk = i >> 6, co = i & 63;
        float w;
        if (kk < 96) { int ci = kk / 3, dt = kk - ci * 3; w = timeW[co * 96 + ci * 3 + dt]; }
        else         { w = resW[co * 16 + (kk - 96)]; }
        As[i] = w;
    }
    if (tid < 64) { sBias[tid] = timeB[tid] + resB[tid]; sG[tid] = gamma[tid]; sBt[tid] = beta[tid]; }
    __syncthreads();

    int g = tid >> 6, co = tid & 63;
    int lane = tid & 31, wsub = (tid >> 5) & 1;

    for (int round = 0; round < 8; round++) {
        int unit = blockIdx.x * 32 + round * 4 + g;   // 0..39999
        int b = unit / NN, n = unit - b * NN;

        // build Z: kk<96 -> time-conv patch (ci,dt), kk>=96 -> residual X
        const float* cbase = g_cheb + n * 1024 + b * 256;       // [tau*32+ci]
        const float* xbase = X + (size_t)(b * NN + n) * 128;    // [f*8+t]
        float* Z = Zs[g];
        for (int i = co; i < 896; i += 64) {
            int kk = i >> 3, t = i & 7;
            float v;
            if (kk < 96) {
                int ci = kk / 3, dt = kk - ci * 3;
                int tau = t + dt - 1;
                v = (tau >= 0 && tau < TT) ? cbase[tau * 32 + ci] : 0.f;
            } else {
                v = xbase[(kk - 96) * 8 + t];
            }
            Z[i] = v;
        }
        __syncthreads();

        float bco = sBias[co];
        unsigned long long y01 = pk2(bco, bco);
        unsigned long long y23 = pk2(bco, bco);
        unsigned long long y45 = pk2(bco, bco);
        unsigned long long y67 = pk2(bco, bco);
        const float4* Z4 = reinterpret_cast<const float4*>(Z);
        const float*  Ap = As + co;
#pragma unroll 4
        for (int kk = 0; kk < 112; kk++) {
            float a = Ap[kk * 64];
            unsigned long long aa = pk2(a, a);
            float4 z0 = Z4[kk * 2];
            float4 z1 = Z4[kk * 2 + 1];
            fma2(y01, aa, pk2(z0.x, z0.y));
            fma2(y23, aa, pk2(z0.z, z0.w));
            fma2(y45, aa, pk2(z1.x, z1.y));
            fma2(y67, aa, pk2(z1.z, z1.w));
        }
        float y[8];
        { float2 p = upk2(y01); y[0] = p.x; y[1] = p.y; }
        { float2 p = upk2(y23); y[2] = p.x; y[3] = p.y; }
        { float2 p = upk2(y45); y[4] = p.x; y[5] = p.y; }
        { float2 p = upk2(y67); y[6] = p.x; y[7] = p.y; }
#pragma unroll
        for (int t = 0; t < 8; t++) y[t] = fmaxf(y[t], 0.f);

        // LayerNorm over 64 channels — two-pass (matches jnp.var semantics)
        float s[8];
#pragma unroll
        for (int t = 0; t < 8; t++) s[t] = y[t];
#pragma unroll
        for (int off = 16; off > 0; off >>= 1) {
#pragma unroll
            for (int t = 0; t < 8; t++) s[t] += __shfl_xor_sync(0xffffffffu, s[t], off);
        }
        if (lane == 0) {
#pragma unroll
            for (int t = 0; t < 8; t++) redS[g][wsub][t] = s[t];
        }
        __syncthreads();

        float mu[8], q[8];
#pragma unroll
        for (int t = 0; t < 8; t++) {
            mu[t] = (redS[g][0][t] + redS[g][1][t]) * (1.f / 64.f);
            float d = y[t] - mu[t];
            q[t] = d * d;
        }
#pragma unroll
        for (int off = 16; off > 0; off >>= 1) {
#pragma unroll
            for (int t = 0; t < 8; t++) q[t] += __shfl_xor_sync(0xffffffffu, q[t], off);
        }
        if (lane == 0) {
#pragma unroll
            for (int t = 0; t < 8; t++) redQ[g][wsub][t] = q[t];
        }
        __syncthreads();

        float ov[8];
#pragma unroll
        for (int t = 0; t < 8; t++) {
            float var = (redQ[g][0][t] + redQ[g][1][t]) * (1.f / 64.f);
            float inv = rsqrtf(var + 1e-5f);
            ov[t] = (y[t] - mu[t]) * inv * sG[co] + sBt[co];
        }
        float4* op = reinterpret_cast<float4*>(out + ((size_t)unit * 64 + co) * 8);
        op[0] = make_float4(ov[0], ov[1], ov[2], ov[3]);
        op[1] = make_float4(ov[4], ov[5], ov[6], ov[7]);
    }
}

// ---------------- launch ----------------
extern "C" void kernel_launch(void* const* d_in, const int* in_sizes, int n_in,
                              void* d_out, int out_size) {
    const float* X     = (const float*)d_in[0];
    const int*   ei    = (const int*)  d_in[1];
    const float* chebW = (const float*)d_in[2];
    const float* chebB = (const float*)d_in[3];
    const float* timeW = (const float*)d_in[4];
    const float* timeB = (const float*)d_in[5];
    const float* resW  = (const float*)d_in[6];
    const float* resB  = (const float*)d_in[7];
    const float* gam   = (const float*)d_in[8];
    const float* bet   = (const float*)d_in[9];
    float* out = (float*)d_out;

    int E = in_sizes[1] / 2;
    const int* src = ei;
    const int* dst = ei + E;
    int EB = (E + 255) / 256;

    k_zero<<<(NN + 255) / 256, 256>>>();
    k_hist<<<EB, 256>>>(dst, E);
    k_scan<<<1, 1024>>>();
    k_fill<<<EB, 256>>>(src, dst, E);
    k_power<<<PB, PT>>>();
    k_permute<<<(TOTX + 255) / 256, 256>>>(X);
    k_lhat1<<<NN, 128>>>();
    k_lhat2cheb<<<NN, 128>>>(chebW, chebB);
    k_final<<<1250, 256>>>(X, timeW, timeB, resW, resB, gam, bet, out);
}

// round 7
// speedup vs baseline: 1.2141x; 1.2141x over previous
#include <cuda_runtime.h>
#include <stdint.h>

// Problem constants (fixed shapes)
#define NN   10000       // nodes
#define BB   4           // batch
#define FIN  16          // input features
#define TT   8           // time steps
#define CCH  32          // cheb channels
#define CTM  64          // time channels
#define MAXE 160000      // edges
#define ITERS 64         // power iterations
#define PB   40          // power-iteration blocks (co-resident, < 148 SMs)
#define PT   256
#define TOTX (NN*512)    // Tx element count = N * TB(32) * F(16)

// ---------------- scratch (device globals; no allocation) ----------------
__device__ __align__(16) float g_Tx0[TOTX];
__device__ __align__(16) float g_Tx1[TOTX];
__device__ __align__(16) float g_cheb[NN*1024];   // [n][tb(32)][c(32)]
__device__ int   g_indeg[NN];
__device__ int   g_rowptr[NN+1];
__device__ int   g_cursor[NN];
__device__ int   g_col[MAXE];
__device__ __align__(16) float g_u0[NN];
__device__ __align__(16) float g_u1[NN];
__device__ float g_S[ITERS+1];
__device__ float g_lmax;
__device__ float g_diag[NN];
__device__ int   g_bar_count;
__device__ int   g_bar_gen;

// ---------------- packed f32x2 helpers (sm_100a) -------------------------
__device__ __forceinline__ unsigned long long pk2(float a, float b) {
    unsigned long long r;
    asm("mov.b64 %0, {%1, %2};" : "=l"(r) : "f"(a), "f"(b));
    return r;
}
__device__ __forceinline__ void fma2(unsigned long long& d, unsigned long long a, unsigned long long b) {
    asm("fma.rn.f32x2 %0, %1, %2, %0;" : "+l"(d) : "l"(a), "l"(b));
}
__device__ __forceinline__ float2 upk2(unsigned long long v) {
    float2 f;
    asm("mov.b64 {%0, %1}, %2;" : "=f"(f.x), "=f"(f.y) : "l"(v));
    return f;
}

// ---------------- software grid barrier (PB co-resident blocks) ----------
// Arrival: one atomicAdd per block. Wait: plain L2 load + nanosleep backoff
// (no RMW storm, no hot-spin burning issue slots).
__device__ __forceinline__ void grid_bar() {
    __syncthreads();
    if (threadIdx.x == 0) {
        int g = __ldcg(&g_bar_gen);
        __threadfence();
        if (atomicAdd(&g_bar_count, 1) == PB - 1) {
            atomicExch(&g_bar_count, 0);
            __threadfence();
            atomicAdd(&g_bar_gen, 1);
        } else {
            while (__ldcg(&g_bar_gen) == g) __nanosleep(32);
            __threadfence();
        }
    }
    __syncthreads();
}

// ---------------- CSR build --------------------------------------------
__global__ void k_zero() {
    int i = blockIdx.x * blockDim.x + threadIdx.x;
    if (i < NN) g_indeg[i] = 0;
}

__global__ void k_hist(const int* __restrict__ dst, int E) {
    int e = blockIdx.x * blockDim.x + threadIdx.x;
    if (e < E) atomicAdd(&g_indeg[dst[e]], 1);
}

__global__ void k_scan() {   // 1 block, 1024 threads
    __shared__ int ps[1024];
    const int CH = 10;       // 1024*10 >= NN
    int t = threadIdx.x;
    int base = t * CH;
    int sum = 0;
#pragma unroll
    for (int i = 0; i < CH; i++) { int idx = base + i; if (idx < NN) sum += g_indeg[idx]; }
    ps[t] = sum; __syncthreads();
    for (int off = 1; off < 1024; off <<= 1) {
        int v = ps[t];
        int a = (t >= off) ? ps[t - off] : 0;
        __syncthreads();
        ps[t] = v + a;
        __syncthreads();
    }
    int run = (t == 0) ? 0 : ps[t - 1];
#pragma unroll
    for (int i = 0; i < CH; i++) {
        int idx = base + i;
        if (idx < NN) { g_rowptr[idx] = run; g_cursor[idx] = run; run += g_indeg[idx]; }
    }
    if (t == 1023) g_rowptr[NN] = ps[1023];
}

__global__ void k_fill(const int* __restrict__ src, const int* __restrict__ dst, int E) {
    int e = blockIdx.x * blockDim.x + threadIdx.x;
    if (e < E) {
        int p = atomicAdd(&g_cursor[dst[e]], 1);
        g_col[p] = src[e];
    }
}

// ---------------- power iteration (persistent, 64 iters) ----------------
// Iteration 1: v0 = const c is in the null space of L, so M v0 is pure fp32
// rounding residue, replicated exactly (chain-sum, unfused mul/sub).
// Iterations 2+: the whole 40KB iterate is staged into shared memory per
// block (coalesced __ldcg float4), so per-edge gathers are LDS ops instead
// of ~250-cycle L2 gathers. Accumulation order identical to round 5.
__global__ void k_power() {
    __shared__ __align__(16) float sm[NN];   // full iterate vector (40 KB)
    __shared__ float red[PT];
    const int TH = PB * PT;
    const float C0 = 0.01f;                  // 1/sqrt(10000) rounded to f32
    int gt = blockIdx.x * PT + threadIdx.x;

    for (int i = gt; i <= ITERS; i += TH) g_S[i] = (i == 0) ? 1.0f : 0.0f;

    bool valid = gt < NN;
    int n = gt;
    int e0 = 0, m = 0; float degf = 0.f;
    if (valid) {
        e0 = g_rowptr[n];
        m  = g_rowptr[n + 1] - e0;
        degf = (float)m;                     // indeg == CSR row length
    }
    grid_bar();

    float* ua = g_u0;
    float* ub = g_u1;
    for (int k = 1; k <= ITERS; k++) {
        float part = 0.0f;
        if (k == 1) {
            if (valid) {
                float av = 0.0f;
                for (int j = 0; j < m; j++) av = __fadd_rn(av, C0);
                float w = __fsub_rn(__fmul_rn(degf, C0), av);
                ub[n] = w;
                part = w * w;
            }
        } else {
            // stage ua (other SMs' writes -> must bypass L1 with ldcg)
            const float4* ua4 = reinterpret_cast<const float4*>(ua);
            float4* sm4 = reinterpret_cast<float4*>(sm);
            for (int i = threadIdx.x; i < NN / 4; i += PT)
                sm4[i] = __ldcg(ua4 + i);
            __syncthreads();

            float inv = 1.0f / sqrtf(__ldcg(&g_S[k - 1]));
            if (valid) {
                float acc = degf * sm[n];
#pragma unroll 4
                for (int j = 0; j < m; j++) acc -= sm[g_col[e0 + j]];
                acc *= inv;
                ub[n] = acc;
                part = acc * acc;
            }
        }
        red[threadIdx.x] = part; __syncthreads();
        for (int s = PT / 2; s > 0; s >>= 1) {
            if (threadIdx.x < s) red[threadIdx.x] += red[threadIdx.x + s];
            __syncthreads();
        }
        if (threadIdx.x == 0) atomicAdd(&g_S[k], red[0]);
        grid_bar();
        float* tmp = ua; ua = ub; ub = tmp;
    }
    float lm = sqrtf(__ldcg(&g_S[ITERS]));
    if (gt == 0) g_lmax = lm;
    for (int i = gt; i < NN; i += TH)
        g_diag[i] = 2.0f * (float)g_indeg[i] / lm - 1.0f;
}

// ---------------- permute X -> Tx0 [n2][tb][f] --------------------------
// Reference: (B,N,F,T) -transpose(2,0,1,3)-> (F,B,N,T) -reshape-> (N2,F2,TB) -transpose(2,0,1)
__global__ void k_permute(const float* __restrict__ X) {
    int o = blockIdx.x * blockDim.x + threadIdx.x;
    if (o >= TOTX) return;
    int n2 = o >> 9;
    int r  = o & 511;
    int tb = r >> 4, f2 = r & 15;
    int s = (n2 << 9) + (f2 << 5) + tb;        // flat idx in (F,B,N,T)
    int f  = s / 320000; int s2 = s - f * 320000;   // 320000 = B*N*T
    int b  = s2 / 80000; int s3 = s2 - b * 80000;   // 80000 = N*T
    int n  = s3 >> 3;    int t  = s3 & 7;
    g_Tx0[o] = X[(((b * NN + n) << 4) + f) * 8 + t];
}

// ---------------- lhat1: Tx1 = diag*Tx0 - off * A^T Tx0 -----------------
__global__ void k_lhat1() {
    int n = blockIdx.x;
    int t = threadIdx.x;   // 0..127, float4 chunk of the 512-channel row
    const float4* x0 = reinterpret_cast<const float4*>(g_Tx0);
    float4 acc = make_float4(0.f, 0.f, 0.f, 0.f);
    int e0 = g_rowptr[n], e1 = g_rowptr[n + 1];
    for (int j = e0; j < e1; j++) {
        int s = g_col[j];
        float4 v = x0[s * 128 + t];
        acc.x += v.x; acc.y += v.y; acc.z += v.z; acc.w += v.w;
    }
    float off = 2.0f / g_lmax;
    float dg  = g_diag[n];
    float4 xx = x0[n * 128 + t];
    float4 o;
    o.x = dg * xx.x - off * acc.x;
    o.y = dg * xx.y - off * acc.y;
    o.z = dg * xx.z - off * acc.z;
    o.w = dg * xx.w - off * acc.w;
    reinterpret_cast<float4*>(g_Tx1)[n * 128 + t] = o;
}

// ------- lhat2 (Tx2 = 2*lhat(Tx1)-Tx0) fused with Cheb GEMM + ReLU ------
__global__ void k_lhat2cheb(const float* __restrict__ chebW, const float* __restrict__ chebB) {
    __shared__ __align__(16) float sT[1536];   // Tx0,Tx1,Tx2 rows of this node
    __shared__ float sW[1536];                 // cheb_W (3,16,32)
    __shared__ float sB[CCH];
    int n = blockIdx.x;
    int t = threadIdx.x;   // 128 threads
    for (int i = t; i < 1536; i += 128) sW[i] = chebW[i];
    if (t < CCH) sB[t] = chebB[t];

    const float4* x0 = reinterpret_cast<const float4*>(g_Tx0);
    const float4* x1 = reinterpret_cast<const float4*>(g_Tx1);
    float4 acc = make_float4(0.f, 0.f, 0.f, 0.f);
    int e0 = g_rowptr[n], e1 = g_rowptr[n + 1];
    for (int j = e0; j < e1; j++) {
        int s = g_col[j];
        float4 v = x1[s * 128 + t];
        acc.x += v.x; acc.y += v.y; acc.z += v.z; acc.w += v.w;
    }
    float off = 2.0f / g_lmax;
    float dg  = g_diag[n];
    float4 a1 = x1[n * 128 + t];
    float4 a0 = x0[n * 128 + t];
    float4 t2;
    t2.x = 2.f * (dg * a1.x - off * acc.x) - a0.x;
    t2.y = 2.f * (dg * a1.y - off * acc.y) - a0.y;
    t2.z = 2.f * (dg * a1.z - off * acc.z) - a0.z;
    t2.w = 2.f * (dg * a1.w - off * acc.w) - a0.w;
    reinterpret_cast<float4*>(sT)[t]       = a0;   // Tx0 row
    reinterpret_cast<float4*>(sT)[128 + t] = a1;   // Tx1 row
    reinterpret_cast<float4*>(sT)[256 + t] = t2;   // Tx2 row
    __syncthreads();

    // out[tb][c] = relu(b_c + sum_k sum_f Txk[tb][f]*W[k][f][c])
    int tb = t >> 2;
    int c0 = (t & 3) << 3;   // 8 channels per thread
    float y[8];
#pragma unroll
    for (int i = 0; i < 8; i++) y[i] = 0.f;
#pragma unroll
    for (int k = 0; k < 3; k++) {
        const float* xr = sT + k * 512 + tb * 16;
        const float* wk = sW + k * 512;
#pragma unroll
        for (int f = 0; f < FIN; f++) {
            float xv = xr[f];
            const float* wr = wk + f * 32 + c0;
#pragma unroll
            for (int i = 0; i < 8; i++) y[i] += xv * wr[i];
        }
    }
    float* outp = g_cheb + n * 1024 + tb * 32 + c0;
#pragma unroll
    for (int i = 0; i < 8; i++) outp[i] = fmaxf(y[i] + sB[c0 + i], 0.f);
}

// ------- final: time conv + residual + ReLU + LayerNorm + write ---------
// per (b,n) unit: Y(64x8) = A(64x112) * Z(112x8) + bias ; relu ; LN over 64
// GEMM uses packed fma.rn.f32x2 (identical rounding to scalar FFMA chain).
__global__ void k_final(const float* __restrict__ X,
                        const float* __restrict__ timeW, const float* __restrict__ timeB,
                        const float* __restrict__ resW,  const float* __restrict__ resB,
                        const float* __restrict__ gamma, const float* __restrict__ beta,
                        float* __restrict__ out) {
    __shared__ float As[112 * 64];                   // transposed: As[kk*64+co]
    __shared__ __align__(16) float Zs[4][896];       // per-group Z (112x8)
    __shared__ float sBias[64], sG[64], sBt[64];
    __shared__ float redS[4][2][8], redQ[4][2][8];
    int tid = threadIdx.x;

    for (int i = tid; i < 7168; i += 256) {
        int kk = i >> 6, co = i & 63;
        float w;
        if (kk < 96) { int ci = kk / 3, dt = kk - ci * 3; w = timeW[co * 96 + ci * 3 + dt]; }
        else         { w = resW[co * 16 + (kk - 96)]; }
        As[i] = w;
    }
    if (tid < 64) { sBias[tid] = timeB[tid] + resB[tid]; sG[tid] = gamma[tid]; sBt[tid] = beta[tid]; }
    __syncthreads();

    int g = tid >> 6, co = tid & 63;
    int lane = tid & 31, wsub = (tid >> 5) & 1;

    for (int round = 0; round < 8; round++) {
        int unit = blockIdx.x * 32 + round * 4 + g;   // 0..39999
        int b = unit / NN, n = unit - b * NN;

        // build Z: kk<96 -> time-conv patch (ci,dt), kk>=96 -> residual X
        const float* cbase = g_cheb + n * 1024 + b * 256;       // [tau*32+ci]
        const float* xbase = X + (size_t)(b * NN + n) * 128;    // [f*8+t]
        float* Z = Zs[g];
        for (int i = co; i < 896; i += 64) {
            int kk = i >> 3, t = i & 7;
            float v;
            if (kk < 96) {
                int ci = kk / 3, dt = kk - ci * 3;
                int tau = t + dt - 1;
                v = (tau >= 0 && tau < TT) ? cbase[tau * 32 + ci] : 0.f;
            } else {
                v = xbase[(kk - 96) * 8 + t];
            }
            Z[i] = v;
        }
        __syncthreads();

        float bco = sBias[co];
        unsigned long long y01 = pk2(bco, bco);
        unsigned long long y23 = pk2(bco, bco);
        unsigned long long y45 = pk2(bco, bco);
        unsigned long long y67 = pk2(bco, bco);
        const float4* Z4 = reinterpret_cast<const float4*>(Z);
        const float*  Ap = As + co;
#pragma unroll 4
        for (int kk = 0; kk < 112; kk++) {
            float a = Ap[kk * 64];
            unsigned long long aa = pk2(a, a);
            float4 z0 = Z4[kk * 2];
            float4 z1 = Z4[kk * 2 + 1];
            fma2(y01, aa, pk2(z0.x, z0.y));
            fma2(y23, aa, pk2(z0.z, z0.w));
            fma2(y45, aa, pk2(z1.x, z1.y));
            fma2(y67, aa, pk2(z1.z, z1.w));
        }
        float y[8];
        { float2 p = upk2(y01); y[0] = p.x; y[1] = p.y; }
        { float2 p = upk2(y23); y[2] = p.x; y[3] = p.y; }
        { float2 p = upk2(y45); y[4] = p.x; y[5] = p.y; }
        { float2 p = upk2(y67); y[6] = p.x; y[7] = p.y; }
#pragma unroll
        for (int t = 0; t < 8; t++) y[t] = fmaxf(y[t], 0.f);

        // LayerNorm over 64 channels — two-pass (matches jnp.var semantics)
        float s[8];
#pragma unroll
        for (int t = 0; t < 8; t++) s[t] = y[t];
#pragma unroll
        for (int off = 16; off > 0; off >>= 1) {
#pragma unroll
            for (int t = 0; t < 8; t++) s[t] += __shfl_xor_sync(0xffffffffu, s[t], off);
        }
        if (lane == 0) {
#pragma unroll
            for (int t = 0; t < 8; t++) redS[g][wsub][t] = s[t];
        }
        __syncthreads();

        float mu[8], q[8];
#pragma unroll
        for (int t = 0; t < 8; t++) {
            mu[t] = (redS[g][0][t] + redS[g][1][t]) * (1.f / 64.f);
            float d = y[t] - mu[t];
            q[t] = d * d;
        }
#pragma unroll
        for (int off = 16; off > 0; off >>= 1) {
#pragma unroll
            for (int t = 0; t < 8; t++) q[t] += __shfl_xor_sync(0xffffffffu, q[t], off);
        }
        if (lane == 0) {
#pragma unroll
            for (int t = 0; t < 8; t++) redQ[g][wsub][t] = q[t];
        }
        __syncthreads();

        float ov[8];
#pragma unroll
        for (int t = 0; t < 8; t++) {
            float var = (redQ[g][0][t] + redQ[g][1][t]) * (1.f / 64.f);
            float inv = rsqrtf(var + 1e-5f);
            ov[t] = (y[t] - mu[t]) * inv * sG[co] + sBt[co];
        }
        float4* op = reinterpret_cast<float4*>(out + ((size_t)unit * 64 + co) * 8);
        op[0] = make_float4(ov[0], ov[1], ov[2], ov[3]);
        op[1] = make_float4(ov[4], ov[5], ov[6], ov[7]);
    }
}

// ---------------- launch ----------------
extern "C" void kernel_launch(void* const* d_in, const int* in_sizes, int n_in,
                              void* d_out, int out_size) {
    const float* X     = (const float*)d_in[0];
    const int*   ei    = (const int*)  d_in[1];
    const float* chebW = (const float*)d_in[2];
    const float* chebB = (const float*)d_in[3];
    const float* timeW = (const float*)d_in[4];
    const float* timeB = (const float*)d_in[5];
    const float* resW  = (const float*)d_in[6];
    const float* resB  = (const float*)d_in[7];
    const float* gam   = (const float*)d_in[8];
    const float* bet   = (const float*)d_in[9];
    float* out = (float*)d_out;

    int E = in_sizes[1] / 2;
    const int* src = ei;
    const int* dst = ei + E;
    int EB = (E + 255) / 256;

    k_zero<<<(NN + 255) / 256, 256>>>();
    k_hist<<<EB, 256>>>(dst, E);
    k_scan<<<1, 1024>>>();
    k_fill<<<EB, 256>>>(src, dst, E);
    k_power<<<PB, PT>>>();
    k_permute<<<(TOTX + 255) / 256, 256>>>(X);
    k_lhat1<<<NN, 128>>>();
    k_lhat2cheb<<<NN, 128>>>(chebW, chebB);
    k_final<<<1250, 256>>>(X, timeW, timeB, resW, resB, gam, bet, out);
}